// round 12
// baseline (speedup 1.0000x reference)
#include <cuda_runtime.h>
#include <cuda_bf16.h>
#include <math.h>
#include <stdint.h>

// Problem constants
#define B_ 4
#define N_ 256
#define D_ 512
#define H_ 8
#define HD_ 64
#define KSP_ 25

typedef unsigned long long u64;

// ---------------- scratch arena (no allocations allowed) ----------------
#define OFF_QKV   0u            // 4*256*1536 = 1572864
#define OFF_ATT   1572864u      // 524288
#define OFF_A0    2097152u      // 524288
#define OFF_A1    2621440u      // 262144
#define OFF_A2    2883584u      // 131072
#define OFF_CUR1  3014656u      // 262144
#define OFF_CUR2  3276800u      // 131072
#define OFF_P1    3407872u      // 262144
#define OFF_P2    3670016u      // 524288
#define OFF_HIER  4194304u      // 524288
#define OFF_HI    4718592u      // 524288
#define OFF_HJ    5242880u      // 524288
#define SCRATCH_TOTAL 5767168u

__device__ float g_scratch[SCRATCH_TOTAL];

// ---------------- f32x2 packed-math helpers ---------------------------------
__device__ __forceinline__ void ffma2(u64& d, u64 a, u64 b) {
    asm("fma.rn.f32x2 %0, %1, %2, %0;" : "+l"(d) : "l"(a), "l"(b));
}
__device__ __forceinline__ float2 up2(u64 v) {
    float2 f; asm("mov.b64 {%0, %1}, %2;" : "=f"(f.x), "=f"(f.y) : "l"(v)); return f;
}

// ---------------- scalar GEMM (PROVEN NUMERICS — R3 bitwise): ----------------
// C = act(A[M,K] @ W[K,N] + bias). Sequential-k FMA chain per output element
// (matches reference rounding pattern; top-k safe — DO NOT change accumulation
// order or split K). BN=64, BK=16, 128 threads.
// BM=32: per-thread 4 rows x 4 cols (8 FFMA2/k).  Use when grid is large.
// BM=16: per-thread 2 rows x 4 cols (4 FFMA2/k).  Doubles grid for small GEMMs
//        so >=2 blocks co-reside per SM (2 warps/SMSP latency hiding).
// Per-output FFMA2 chain identical across BM variants -> bitwise-same results.
// ACT: 0 none, 1 relu, 2 pairwise-mean epilogue (writes M/2 rows).
// GATHER=1: A rows gathered from 3-level concat (A | g1 x2-up | g2 x4-up).
// blockIdx.z==1 selects (Wb, biasb, Cb) — fuses hi+hj into one launch.
template<int ACT, int GATHER, int BM>
__global__ __launch_bounds__(128, 4)
void gemmS(const float* __restrict__ A, const float* __restrict__ W,
           const float* __restrict__ bias, float* __restrict__ C,
           int M, int N, int K,
           const float* __restrict__ g1, const float* __restrict__ g2,
           const float* __restrict__ Wb, const float* __restrict__ biasb,
           float* __restrict__ Cb)
{
    if (blockIdx.z == 1) { W = Wb; bias = biasb; C = Cb; }
    constexpr int RPT = (BM == 32) ? 4 : 2;          // rows per thread
    __shared__ __align__(16) u64   As2[2][16][BM + 2]; // duplicated A values [k][m]
    __shared__ __align__(16) float Ws [2][16][68];     // [k][n]
    const int tid = threadIdx.x;
    const int tx = tid & 15, ty = tid >> 4;            // 16 col-groups x 8 row-groups
    const int row0 = blockIdx.y * BM, col0 = blockIdx.x * 64;

    // staging: A tile BM x 16 floats; W tile 16 x 64 (2 float4 per thread)
    const int ar_ = tid >> 2;            // A row (BM32: 0..31 over all threads; BM16: tid<64)
    const int akc = (tid & 3) * 4;       // A k 0,4,8,12
    const int wk  = tid >> 4;            // W k 0..7 (and +8)
    const int wn  = (tid & 15) * 4;      // W n
    const bool doA = (BM == 32) || (tid < 64);

    u64 acc[RPT][2];
    #pragma unroll
    for (int i = 0; i < RPT; i++) { acc[i][0] = 0ull; acc[i][1] = 0ull; }

    const int KT = K >> 4;
    float4 av, wv0, wv1;

    auto gload = [&](int kt) {
        const int k0 = kt * 16;
        if (doA) {
            if (GATHER) {
                int rg = row0 + ar_, k = k0 + akc;
                int bb = rg >> 8, node = rg & 255;
                const float* p;
                if (k < 512)       p = &A [(size_t)rg * 512 + k];
                else if (k < 1024) p = &g1[(size_t)(bb * 128 + (node >> 1)) * 512 + (k - 512)];
                else               p = &g2[(size_t)(bb * 64 + (node >> 2)) * 512 + (k - 1024)];
                av = *(const float4*)p;
            } else {
                av = *(const float4*)&A[(size_t)(row0 + ar_) * K + k0 + akc];
            }
        }
        wv0 = *(const float4*)&W[(size_t)(k0 + wk) * N + col0 + wn];
        wv1 = *(const float4*)&W[(size_t)(k0 + wk + 8) * N + col0 + wn];
    };
    auto sstore = [&](int buf) {
        if (doA) {
            *(float2*)&As2[buf][akc + 0][ar_] = make_float2(av.x, av.x);
            *(float2*)&As2[buf][akc + 1][ar_] = make_float2(av.y, av.y);
            *(float2*)&As2[buf][akc + 2][ar_] = make_float2(av.z, av.z);
            *(float2*)&As2[buf][akc + 3][ar_] = make_float2(av.w, av.w);
        }
        *(float4*)&Ws[buf][wk][wn]     = wv0;
        *(float4*)&Ws[buf][wk + 8][wn] = wv1;
    };

    gload(0); sstore(0);
    __syncthreads();
    for (int kt = 0; kt < KT; kt++) {
        const int buf = kt & 1;
        if (kt + 1 < KT) gload(kt + 1);

        // register-pipelined fragment loads: prefetch k+1 while computing k.
        // The ffma2 issue order per accumulator is unchanged (k ascending).
        if (BM == 32) {
            ulonglong2 a01 = *(const ulonglong2*)&As2[buf][0][ty * 4];
            ulonglong2 a23 = *(const ulonglong2*)&As2[buf][0][ty * 4 + 2];
            ulonglong2 bq  = *(const ulonglong2*)&Ws[buf][0][tx * 4];
            #pragma unroll
            for (int k = 0; k < 16; k++) {
                ulonglong2 na01, na23, nbq;
                if (k < 15) {
                    na01 = *(const ulonglong2*)&As2[buf][k + 1][ty * 4];
                    na23 = *(const ulonglong2*)&As2[buf][k + 1][ty * 4 + 2];
                    nbq  = *(const ulonglong2*)&Ws[buf][k + 1][tx * 4];
                }
                ffma2(acc[0][0], a01.x, bq.x); ffma2(acc[0][1], a01.x, bq.y);
                ffma2(acc[1][0], a01.y, bq.x); ffma2(acc[1][1], a01.y, bq.y);
                ffma2(acc[2][0], a23.x, bq.x); ffma2(acc[2][1], a23.x, bq.y);
                ffma2(acc[RPT - 1][0], a23.y, bq.x); ffma2(acc[RPT - 1][1], a23.y, bq.y);
                if (k < 15) { a01 = na01; a23 = na23; bq = nbq; }
            }
        } else {
            ulonglong2 a01 = *(const ulonglong2*)&As2[buf][0][ty * 2];
            ulonglong2 bq  = *(const ulonglong2*)&Ws[buf][0][tx * 4];
            #pragma unroll
            for (int k = 0; k < 16; k++) {
                ulonglong2 na01, nbq;
                if (k < 15) {
                    na01 = *(const ulonglong2*)&As2[buf][k + 1][ty * 2];
                    nbq  = *(const ulonglong2*)&Ws[buf][k + 1][tx * 4];
                }
                ffma2(acc[0][0], a01.x, bq.x); ffma2(acc[0][1], a01.x, bq.y);
                ffma2(acc[1][0], a01.y, bq.x); ffma2(acc[1][1], a01.y, bq.y);
                if (k < 15) { a01 = na01; bq = nbq; }
            }
        }

        if (kt + 1 < KT) sstore(buf ^ 1);
        __syncthreads();
    }

    float4 bv = make_float4(0.f, 0.f, 0.f, 0.f);
    if (bias) bv = *(const float4*)&bias[col0 + tx * 4];

    float v[RPT][4];
    #pragma unroll
    for (int i = 0; i < RPT; i++) {
        float2 p01 = up2(acc[i][0]);
        float2 p23 = up2(acc[i][1]);
        v[i][0] = p01.x + bv.x; v[i][1] = p01.y + bv.y;
        v[i][2] = p23.x + bv.z; v[i][3] = p23.y + bv.w;
        if (ACT == 1) {
            #pragma unroll
            for (int j = 0; j < 4; j++) v[i][j] = fmaxf(v[i][j], 0.f);
        }
    }

    if (ACT == 2) {
        // pairwise mean over row pairs: write M/2 rows
        #pragma unroll
        for (int p = 0; p < RPT / 2; p++) {
            float4 o = make_float4(0.5f * (v[2 * p][0] + v[2 * p + 1][0]),
                                   0.5f * (v[2 * p][1] + v[2 * p + 1][1]),
                                   0.5f * (v[2 * p][2] + v[2 * p + 1][2]),
                                   0.5f * (v[2 * p][3] + v[2 * p + 1][3]));
            const int ro = (BM == 32) ? ((row0 >> 1) + ty * 2 + p) : ((row0 >> 1) + ty);
            *(float4*)&C[(size_t)ro * N + col0 + tx * 4] = o;
        }
    } else {
        #pragma unroll
        for (int i = 0; i < RPT; i++) {
            const int r = (BM == 32) ? (row0 + ty * 4 + i) : (row0 + ty * 2 + i);
            *(float4*)&C[(size_t)r * N + col0 + tx * 4] =
                make_float4(v[i][0], v[i][1], v[i][2], v[i][3]);
        }
    }
}

// ---------------- tf32 helpers (final-MHA-only fast path) --------------------
__device__ __forceinline__ uint32_t tf32_of(float v) {
    uint32_t r; asm("cvt.rna.tf32.f32 %0, %1;" : "=r"(r) : "f"(v)); return r;
}
__device__ __forceinline__ void split2(float v, uint32_t& h, uint32_t& l) {
    h = tf32_of(v);
    l = tf32_of(v - __uint_as_float(h));
}
__device__ __forceinline__ void mma_tf32(float* d, const uint32_t* a, const uint32_t* b) {
    asm("mma.sync.aligned.m16n8k8.row.col.f32.tf32.tf32.f32 "
        "{%0,%1,%2,%3}, {%4,%5,%6,%7}, {%8,%9}, {%0,%1,%2,%3};"
        : "+f"(d[0]), "+f"(d[1]), "+f"(d[2]), "+f"(d[3])
        : "r"(a[0]), "r"(a[1]), "r"(a[2]), "r"(a[3]), "r"(b[0]), "r"(b[1]));
}

// ---------------- tensor-core GEMM (3xTF32, ~1e-5 class) ---------------------
// ONLY for the final sparse-path MHA (feeds output0, threshold 1e-3).
// NOT top-k safe — never use upstream of edge scores.
__global__ __launch_bounds__(256)
void gemm_tc3(const float* __restrict__ A, const float* __restrict__ W,
              const float* __restrict__ bias, float* __restrict__ C,
              int M, int N, int K)
{
    __shared__ uint32_t Ah[2][16][72], Al[2][16][72];
    __shared__ uint32_t Bh[2][16][72], Bl[2][16][72];

    const int tid = threadIdx.x;
    const int lane = tid & 31, wrp = tid >> 5;
    const int row0 = blockIdx.y * 64, col0 = blockIdx.x * 64;
    const int m_w = (wrp >> 2) * 32;
    const int n_w = (wrp & 3) * 16;
    const int g = lane >> 2, tg = lane & 3;

    const int arow = tid >> 2;
    const int akc  = (tid & 3) * 4;
    const int bk   = tid >> 4;
    const int bnc  = (tid & 15) * 4;

    float acc[2][2][4];
    #pragma unroll
    for (int mi = 0; mi < 2; mi++)
        #pragma unroll
        for (int ni = 0; ni < 2; ni++)
            #pragma unroll
            for (int q = 0; q < 4; q++) acc[mi][ni][q] = 0.f;

    const int KT = K >> 4;
    float4 va, vb;

    auto gload = [&](int kt) {
        const int k0 = kt * 16;
        va = *(const float4*)&A[(size_t)(row0 + arow) * K + k0 + akc];
        vb = *(const float4*)&W[(size_t)(k0 + bk) * N + col0 + bnc];
    };
    auto sstore = [&](int buf) {
        uint32_t h, l;
        split2(va.x, h, l); Ah[buf][akc + 0][arow] = h; Al[buf][akc + 0][arow] = l;
        split2(va.y, h, l); Ah[buf][akc + 1][arow] = h; Al[buf][akc + 1][arow] = l;
        split2(va.z, h, l); Ah[buf][akc + 2][arow] = h; Al[buf][akc + 2][arow] = l;
        split2(va.w, h, l); Ah[buf][akc + 3][arow] = h; Al[buf][akc + 3][arow] = l;
        uint4 h4, l4;
        split2(vb.x, h4.x, l4.x);
        split2(vb.y, h4.y, l4.y);
        split2(vb.z, h4.z, l4.z);
        split2(vb.w, h4.w, l4.w);
        *(uint4*)&Bh[buf][bk][bnc] = h4;
        *(uint4*)&Bl[buf][bk][bnc] = l4;
    };

    gload(0); sstore(0);
    __syncthreads();
    for (int kt = 0; kt < KT; kt++) {
        const int buf = kt & 1;
        if (kt + 1 < KT) gload(kt + 1);
        #pragma unroll
        for (int ks = 0; ks < 16; ks += 8) {
            uint32_t ah[2][4], al[2][4], bh[2][2], bl[2][2];
            #pragma unroll
            for (int mi = 0; mi < 2; mi++) {
                const int m = m_w + mi * 16;
                ah[mi][0] = Ah[buf][ks + tg][m + g];
                ah[mi][1] = Ah[buf][ks + tg][m + g + 8];
                ah[mi][2] = Ah[buf][ks + tg + 4][m + g];
                ah[mi][3] = Ah[buf][ks + tg + 4][m + g + 8];
                al[mi][0] = Al[buf][ks + tg][m + g];
                al[mi][1] = Al[buf][ks + tg][m + g + 8];
                al[mi][2] = Al[buf][ks + tg + 4][m + g];
                al[mi][3] = Al[buf][ks + tg + 4][m + g + 8];
            }
            #pragma unroll
            for (int ni = 0; ni < 2; ni++) {
                const int n = n_w + ni * 8;
                bh[ni][0] = Bh[buf][ks + tg][n + g];
                bh[ni][1] = Bh[buf][ks + tg + 4][n + g];
                bl[ni][0] = Bl[buf][ks + tg][n + g];
                bl[ni][1] = Bl[buf][ks + tg + 4][n + g];
            }
            #pragma unroll
            for (int mi = 0; mi < 2; mi++)
                #pragma unroll
                for (int ni = 0; ni < 2; ni++) {
                    mma_tf32(acc[mi][ni], al[mi], bh[ni]);
                    mma_tf32(acc[mi][ni], ah[mi], bl[ni]);
                    mma_tf32(acc[mi][ni], ah[mi], bh[ni]);
                }
        }
        if (kt + 1 < KT) sstore(buf ^ 1);
        __syncthreads();
    }

    #pragma unroll
    for (int mi = 0; mi < 2; mi++) {
        #pragma unroll
        for (int ni = 0; ni < 2; ni++) {
            const int col = col0 + n_w + ni * 8 + 2 * tg;
            float b0 = 0.f, b1 = 0.f;
            if (bias) { b0 = bias[col]; b1 = bias[col + 1]; }
            const int r0 = row0 + m_w + mi * 16 + g;
            *(float2*)&C[(size_t)r0 * N + col] =
                make_float2(acc[mi][ni][0] + b0, acc[mi][ni][1] + b1);
            *(float2*)&C[(size_t)(r0 + 8) * N + col] =
                make_float2(acc[mi][ni][2] + b0, acc[mi][ni][3] + b1);
        }
    }
}

// ---------------- fused flash attention --------------------------------------
// grid (n/32, B*H), 128 threads. qkv [B,n,1536]; out att [B*n, 512] head-packed.
__global__ __launch_bounds__(128)
void flash_attn(const float* __restrict__ qkv, float* __restrict__ att, int n)
{
    __shared__ __align__(16) float Qs[64][36];   // [k][i] transposed
    __shared__ __align__(16) float Ks[64][36];   // [k][j] transposed, 32-j chunk
    __shared__ __align__(16) float Vs[32][68];   // [j][d]
    __shared__ __align__(16) float Ps[32][36];   // [i][j]
    const int bh = blockIdx.y, b = bh >> 3, h = bh & 7;
    const int i0 = blockIdx.x * 32;
    const int tid = threadIdx.x;
    const int tx = tid & 7, ty = tid >> 3;       // ty 0..15 (2 rows), tx 0..7
    const float* qb = qkv + (size_t)b * n * 1536 + h * 64;
    const float* kb = qb + 512;
    const float* vb = qb + 1024;

    #pragma unroll
    for (int t = 0; t < 4; t++) {
        int f = t * 128 + tid;                   // 0..511
        int r = f >> 4, c = (f & 15) * 4;
        float4 q = *(const float4*)&qb[(size_t)(i0 + r) * 1536 + c];
        Qs[c + 0][r] = q.x; Qs[c + 1][r] = q.y; Qs[c + 2][r] = q.z; Qs[c + 3][r] = q.w;
    }

    float Oa[2][8] = {};
    float m[2] = {-1e30f, -1e30f}, l[2] = {0.f, 0.f};

    for (int j0 = 0; j0 < n; j0 += 32) {
        __syncthreads();
        #pragma unroll
        for (int t = 0; t < 4; t++) {
            int f = t * 128 + tid;
            int r = f >> 4, c = (f & 15) * 4;
            float4 kv = *(const float4*)&kb[(size_t)(j0 + r) * 1536 + c];
            Ks[c + 0][r] = kv.x; Ks[c + 1][r] = kv.y; Ks[c + 2][r] = kv.z; Ks[c + 3][r] = kv.w;
            *(float4*)&Vs[r][c] = *(const float4*)&vb[(size_t)(j0 + r) * 1536 + c];
        }
        __syncthreads();

        float s[2][4] = {};
        #pragma unroll
        for (int k = 0; k < 64; k++) {
            float2 q2 = *(const float2*)&Qs[k][ty * 2];
            float4 k4 = *(const float4*)&Ks[k][tx * 4];
            s[0][0] += q2.x * k4.x; s[0][1] += q2.x * k4.y;
            s[0][2] += q2.x * k4.z; s[0][3] += q2.x * k4.w;
            s[1][0] += q2.y * k4.x; s[1][1] += q2.y * k4.y;
            s[1][2] += q2.y * k4.z; s[1][3] += q2.y * k4.w;
        }

        float p[2][4];
        #pragma unroll
        for (int i = 0; i < 2; i++) {
            #pragma unroll
            for (int j = 0; j < 4; j++) s[i][j] *= 0.125f;
            float mc = fmaxf(fmaxf(s[i][0], s[i][1]), fmaxf(s[i][2], s[i][3]));
            #pragma unroll
            for (int o = 1; o < 8; o <<= 1) mc = fmaxf(mc, __shfl_xor_sync(0xffffffffu, mc, o));
            float mn = fmaxf(m[i], mc);
            float sc = expf(m[i] - mn);
            m[i] = mn;
            float ls = 0.f;
            #pragma unroll
            for (int j = 0; j < 4; j++) { p[i][j] = expf(s[i][j] - mn); ls += p[i][j]; }
            #pragma unroll
            for (int o = 1; o < 8; o <<= 1) ls += __shfl_xor_sync(0xffffffffu, ls, o);
            l[i] = l[i] * sc + ls;
            #pragma unroll
            for (int d = 0; d < 8; d++) Oa[i][d] *= sc;
            *(float4*)&Ps[2 * ty + i][tx * 4] = make_float4(p[i][0], p[i][1], p[i][2], p[i][3]);
        }
        __syncthreads();

        #pragma unroll
        for (int j = 0; j < 32; j++) {
            float p0 = Ps[2 * ty][j], p1 = Ps[2 * ty + 1][j];
            float4 v0 = *(const float4*)&Vs[j][tx * 8];
            float4 v1 = *(const float4*)&Vs[j][tx * 8 + 4];
            Oa[0][0] += p0 * v0.x; Oa[0][1] += p0 * v0.y; Oa[0][2] += p0 * v0.z; Oa[0][3] += p0 * v0.w;
            Oa[0][4] += p0 * v1.x; Oa[0][5] += p0 * v1.y; Oa[0][6] += p0 * v1.z; Oa[0][7] += p0 * v1.w;
            Oa[1][0] += p1 * v0.x; Oa[1][1] += p1 * v0.y; Oa[1][2] += p1 * v0.z; Oa[1][3] += p1 * v0.w;
            Oa[1][4] += p1 * v1.x; Oa[1][5] += p1 * v1.y; Oa[1][6] += p1 * v1.z; Oa[1][7] += p1 * v1.w;
        }
    }

    #pragma unroll
    for (int i = 0; i < 2; i++) {
        const float inv = 1.f / l[i];
        float* op = att + (size_t)(b * n + i0 + 2 * ty + i) * 512 + h * 64 + tx * 8;
        *(float4*)op       = make_float4(Oa[i][0] * inv, Oa[i][1] * inv, Oa[i][2] * inv, Oa[i][3] * inv);
        *(float4*)(op + 4) = make_float4(Oa[i][4] * inv, Oa[i][5] * inv, Oa[i][6] * inv, Oa[i][7] * inv);
    }
}

// ---------------- LayerNorm over rows of 512 --------------------------------
__global__ __launch_bounds__(256)
void ln_rows(const float* __restrict__ Hp, const float* __restrict__ g,
             const float* __restrict__ bb, float* __restrict__ out, int rows)
{
    const int warp = (blockIdx.x * 256 + threadIdx.x) >> 5;
    const int lane = threadIdx.x & 31;
    if (warp >= rows) return;
    const float* row = Hp + (size_t)warp * 512;
    float v[16];
    float s = 0.f;
    #pragma unroll
    for (int t = 0; t < 16; t++) { v[t] = row[lane + 32 * t]; s += v[t]; }
    #pragma unroll
    for (int o = 16; o; o >>= 1) s += __shfl_xor_sync(0xffffffffu, s, o);
    const float mean = s * (1.f / 512.f);
    float var = 0.f;
    #pragma unroll
    for (int t = 0; t < 16; t++) { float d = v[t] - mean; var += d * d; }
    #pragma unroll
    for (int o = 16; o; o >>= 1) var += __shfl_xor_sync(0xffffffffu, var, o);
    var *= (1.f / 512.f);
    const float inv = rsqrtf(var + 1e-5f);
    float* o_ = out + (size_t)warp * 512;
    #pragma unroll
    for (int t = 0; t < 16; t++) {
        int c = lane + 32 * t;
        o_[c] = (v[t] - mean) * inv * g[c] + bb[c];
    }
}

// ---------------- fused edge scores + top-25 ---------------------------------
// Block = (b, 8 rows i). Phase 1: warp w computes scores for j in [32w,32w+32)
// for all 8 rows (IDENTICAL fp ops + warp-reduce order as before) into smem.
// Phase 2: warp w selects top-25 of row i0+w (same lexicographic tie-break)
// and writes the one-hot adj row directly. Kills the esc global round-trip.
__global__ __launch_bounds__(256)
void edge_topk(const float* __restrict__ hi, const float* __restrict__ hj,
               const float* __restrict__ We2, const float* __restrict__ be2,
               float* __restrict__ adj)
{
    __shared__ float his[8][512];
    __shared__ float w2s[512];
    __shared__ float sc8[8][260];
    const int blk = blockIdx.x;
    const int b = blk >> 5;
    const int i0 = (blk & 31) * 8;
    const int tid = threadIdx.x;
    #pragma unroll
    for (int q = 0; q < 4; q++) {
        int fi = tid + 256 * q;
        int r = fi >> 7;
        int c = (fi & 127) * 4;
        *(float4*)&his[r][c] = *(const float4*)&hi[(size_t)(b * 256 + i0 + r) * 512 + c];
    }
    w2s[tid] = We2[tid];
    w2s[tid + 256] = We2[tid + 256];
    __syncthreads();

    const int w = tid >> 5, lane = tid & 31;
    const float be2v = be2[0];
    const float* hjb = hj + (size_t)b * 256 * 512;
    for (int jj = 0; jj < 32; jj++) {
        const int j = w * 32 + jj;
        const float* hjr = hjb + (size_t)j * 512;
        float acc[8] = {};
        #pragma unroll 4
        for (int q = 0; q < 16; q++) {
            int d = lane + 32 * q;
            float hv = hjr[d];
            float w2 = w2s[d];
            #pragma unroll
            for (int i = 0; i < 8; i++)
                acc[i] += fmaxf(his[i][d] + hv, 0.f) * w2;
        }
        #pragma unroll
        for (int i = 0; i < 8; i++) {
            float a = acc[i];
            #pragma unroll
            for (int o = 16; o; o >>= 1) a += __shfl_xor_sync(0xffffffffu, a, o);
            acc[i] = a;
        }
        if (lane == 0) {
            #pragma unroll
            for (int i = 0; i < 8; i++) {
                int ii = i0 + i;
                float sv = (j == ii) ? 0.f : 1.f / (1.f + expf(-(acc[i] + be2v)));
                sc8[i][j] = sv;
            }
        }
    }
    __syncthreads();

    // Phase 2: warp w -> row i0 + w
    const int row = b * 256 + i0 + w;
    float* arow = adj + (size_t)row * N_;
    float v[8];
    #pragma unroll
    for (int t = 0; t < 8; t++) { v[t] = sc8[w][lane + 32 * t]; arow[lane + 32 * t] = 0.f; }
    __syncwarp();
    for (int k = 0; k < KSP_; k++) {
        float bvv = -1e30f; int bi = 0x7fffffff;
        #pragma unroll
        for (int t = 0; t < 8; t++) {
            int idx = lane + 32 * t;
            if (v[t] > bvv) { bvv = v[t]; bi = idx; }
        }
        #pragma unroll
        for (int o = 16; o; o >>= 1) {
            float ov = __shfl_xor_sync(0xffffffffu, bvv, o);
            int   oi = __shfl_xor_sync(0xffffffffu, bi, o);
            if (ov > bvv || (ov == bvv && oi < bi)) { bvv = ov; bi = oi; }
        }
        if (lane == (bi & 31)) v[bi >> 5] = -1e30f;
        if (lane == 0) arow[bi] = 1.0f;
    }
}

// ---------------- host orchestration ----------------------------------------
#define GS(ACT, GATHER, BM, GX, GY, GZ, ...) \
    gemmS<ACT, GATHER, BM><<<dim3(GX, GY, GZ), 128>>>(__VA_ARGS__)

// scalar (proven) MHA — used for all hierarchy levels (score-feeding path)
static void run_mha_scalar(const float* cur, const float* Wqkv, const float* bqkv,
                           const float* Wo, const float* bo, float* outp,
                           float* qkv, float* att, int n)
{
    const int M = B_ * n;
    // qkv: BM=32 when grid large enough (M>=512), else BM=16
    if (M >= 512) {
        GS(0, 0, 32, 1536 / 64, M / 32, 1,
           cur, Wqkv, bqkv, qkv, M, 1536, 512, nullptr, nullptr, nullptr, nullptr, nullptr);
    } else {
        GS(0, 0, 16, 1536 / 64, M / 16, 1,
           cur, Wqkv, bqkv, qkv, M, 1536, 512, nullptr, nullptr, nullptr, nullptr, nullptr);
    }
    flash_attn<<<dim3(n / 32, B_ * H_), 128>>>(qkv, att, n);
    // Wo: small N -> BM=16 for grid
    GS(0, 0, 16, 512 / 64, M / 16, 1,
       att, Wo, bo, outp, M, 512, 512, nullptr, nullptr, nullptr, nullptr, nullptr);
}

// tensor-core MHA — used ONLY for the final sparse-path MHA (output0 slack)
static void run_mha_tc(const float* cur, const float* Wqkv, const float* bqkv,
                       const float* Wo, const float* bo, float* outp,
                       float* qkv, float* att, int n)
{
    const int M = B_ * n;
    gemm_tc3<<<dim3(1536 / 64, M / 64), 256>>>(cur, Wqkv, bqkv, qkv, M, 1536, 512);
    flash_attn<<<dim3(n / 32, B_ * H_), 128>>>(qkv, att, n);
    gemm_tc3<<<dim3(512 / 64, M / 64), 256>>>(att, Wo, bo, outp, M, 512, 512);
}

extern "C" void kernel_launch(void* const* d_in, const int* in_sizes, int n_in,
                              void* d_out, int out_size)
{
    const float* x      = (const float*)d_in[0];
    const float* Wqkv   = (const float*)d_in[2];
    const float* bqkv   = (const float*)d_in[3];
    const float* Wo     = (const float*)d_in[4];
    const float* bo     = (const float*)d_in[5];
    const float* Wp1    = (const float*)d_in[6];
    const float* bp1    = (const float*)d_in[7];
    const float* Wp2    = (const float*)d_in[8];
    const float* bp2    = (const float*)d_in[9];
    const float* Wfuse  = (const float*)d_in[10];
    const float* bfuse  = (const float*)d_in[11];
    const float* ln_g   = (const float*)d_in[12];
    const float* ln_b   = (const float*)d_in[13];
    const float* We1    = (const float*)d_in[14];
    const float* be1    = (const float*)d_in[15];
    const float* We2    = (const float*)d_in[16];
    const float* be2    = (const float*)d_in[17];
    const float* Ws_qkv = (const float*)d_in[18];
    const float* bs_qkv = (const float*)d_in[19];
    const float* Ws_o   = (const float*)d_in[20];
    const float* bs_o   = (const float*)d_in[21];
    float* out = (float*)d_out;

    float* sc = nullptr;
    cudaGetSymbolAddress((void**)&sc, g_scratch);
    float* qkv  = sc + OFF_QKV;
    float* att  = sc + OFF_ATT;
    float* a0   = sc + OFF_A0;
    float* a1   = sc + OFF_A1;
    float* a2   = sc + OFF_A2;
    float* cur1 = sc + OFF_CUR1;
    float* cur2 = sc + OFF_CUR2;
    float* p1   = sc + OFF_P1;
    float* p2   = sc + OFF_P2;
    float* hier = sc + OFF_HIER;
    float* hi   = sc + OFF_HI;
    float* hj   = sc + OFF_HJ;

    // ---- hierarchy (score-feeding: scalar proven numerics) ----
    const int ns[3] = {256, 128, 64};
    float* aouts[3] = {a0, a1, a2};
    float* curbuf[2] = {cur1, cur2};
    const float* cur = x;
    for (int l = 0; l < 3; l++) {
        const int n = ns[l];
        const int M = B_ * n;
        run_mha_scalar(cur, Wqkv + (size_t)l * 512 * 1536, bqkv + l * 1536,
                       Wo + (size_t)l * 512 * 512, bo + l * 512, aouts[l], qkv, att, n);
        if (l < 2) {
            GS(1, 0, 16, 256 / 64, M / 16, 1,
               aouts[l], Wp1 + (size_t)l * 512 * 256, bp1 + l * 256, p1, M, 256, 512,
               nullptr, nullptr, nullptr, nullptr, nullptr);
            // Wp2 with fused pairwise-mean epilogue -> writes M/2 rows directly
            GS(2, 0, 16, 512 / 64, M / 16, 1,
               p1, Wp2 + (size_t)l * 256 * 512, bp2 + l * 512, curbuf[l], M, 512, 256,
               nullptr, nullptr, nullptr, nullptr, nullptr);
            cur = curbuf[l];
        }
    }

    // ---- fuse (gathered concat) + LN (score-feeding: scalar) ----
    GS(1, 1, 16, 512 / 64, 1024 / 16, 1,
       a0, Wfuse, bfuse, p2, 1024, 512, 1536, a1, a2, nullptr, nullptr, nullptr);
    ln_rows<<<1024 / 8, 256>>>(p2, ln_g, ln_b, hier, 1024);

    // ---- edge scoring (hi+hj fused via z; scalar) + fused top-k ----
    GS(0, 0, 32, 512 / 64, 1024 / 32, 2,
       hier, We1, nullptr, hi, 1024, 512, 512,
       nullptr, nullptr, We1 + 512 * 512, be1, hj);
    float* adj_out = out + (size_t)B_ * N_ * D_;
    edge_topk<<<B_ * (N_ / 8), 256>>>(hi, hj, We2, be2, adj_out);

    // ---- final sparse-path MHA -> attended (output0 only: tensor cores) ----
    run_mha_tc(hier, Ws_qkv, bs_qkv, Ws_o, bs_o, out, qkv, att, 256);
}

// round 13
// speedup vs baseline: 1.3591x; 1.3591x over previous
#include <cuda_runtime.h>
#include <cuda_bf16.h>
#include <math.h>
#include <stdint.h>

// Problem constants
#define B_ 4
#define N_ 256
#define D_ 512
#define H_ 8
#define HD_ 64
#define KSP_ 25

typedef unsigned long long u64;

// ---------------- scratch arena (no allocations allowed) ----------------
#define OFF_QKV   0u            // 4*256*1536 = 1572864
#define OFF_ATT   1572864u      // 524288
#define OFF_A0    2097152u      // 524288
#define OFF_A1    2621440u      // 262144
#define OFF_A2    2883584u      // 131072
#define OFF_CUR1  3014656u      // 262144
#define OFF_CUR2  3276800u      // 131072
#define OFF_P1    3407872u      // 262144
#define OFF_P2    3670016u      // 524288
#define OFF_HIER  4194304u      // 524288
#define OFF_HI    4718592u      // 524288
#define OFF_HJ    5242880u      // 524288
#define SCRATCH_TOTAL 5767168u

__device__ float g_scratch[SCRATCH_TOTAL];

// ---------------- helpers ----------------------------------------------------
__device__ __forceinline__ void ffma2(u64& d, u64 a, u64 b) {
    asm("fma.rn.f32x2 %0, %1, %2, %0;" : "+l"(d) : "l"(a), "l"(b));
}
__device__ __forceinline__ float2 up2(u64 v) {
    float2 f; asm("mov.b64 {%0, %1}, %2;" : "=f"(f.x), "=f"(f.y) : "l"(v)); return f;
}
__device__ __forceinline__ u64 splat2(float v) {
    u64 r; asm("mov.b64 %0, {%1, %1};" : "=l"(r) : "f"(v)); return r;
}
__device__ __forceinline__ uint32_t smem_u32(const void* p) {
    return (uint32_t)__cvta_generic_to_shared(p);
}
__device__ __forceinline__ void cp_async16(uint32_t dst, const void* src) {
    asm volatile("cp.async.cg.shared.global [%0], [%1], 16;" :: "r"(dst), "l"(src));
}
__device__ __forceinline__ void cp_commit() {
    asm volatile("cp.async.commit_group;" ::: "memory");
}
template<int Nw>
__device__ __forceinline__ void cp_wait() {
    asm volatile("cp.async.wait_group %0;" :: "n"(Nw) : "memory");
}

// ---------------- scalar GEMM (PROVEN NUMERICS — R3 bitwise): ----------------
// C = act(A[M,K] @ W[K,N] + bias). Sequential-k FMA chain per output element
// (matches reference rounding pattern; top-k safe — DO NOT change accumulation
// order or split K). BM=32, BN=64, BK=16, 128 threads, 4x4 per thread.
// R13: 4-stage cp.async global pipeline — hides the per-k-tile LDG latency
// that dominated (k-tile ~1350cyc vs ~300cyc compute). A staged RAW [m][k]
// (cp.async can't duplicate); k-loop splats A scalars. Per-output FFMA2 chain
// (k ascending, identical products) unchanged -> bitwise-same results.
// ACT: 0 none, 1 relu, 2 pairwise-mean epilogue (writes M/2 rows).
// GATHER=1: A rows gathered from 3-level concat (A | g1 x2-up | g2 x4-up).
// blockIdx.z==1 selects (Wb, biasb, Cb) — fuses hi+hj into one launch.
template<int ACT, int GATHER>
__global__ __launch_bounds__(128, 4)
void gemmS(const float* __restrict__ A, const float* __restrict__ W,
           const float* __restrict__ bias, float* __restrict__ C,
           int M, int N, int K,
           const float* __restrict__ g1, const float* __restrict__ g2,
           const float* __restrict__ Wb, const float* __restrict__ biasb,
           float* __restrict__ Cb)
{
    if (blockIdx.z == 1) { W = Wb; bias = biasb; C = Cb; }
    constexpr int ST = 4;
    __shared__ __align__(16) float As[ST][32][20];  // raw A [m][k], 80B rows
    __shared__ __align__(16) float Ws[ST][16][64];  // raw W [k][n]
    const int tid = threadIdx.x;
    const int tx = tid & 15, ty = tid >> 4;         // 16 col-groups x 8 row-groups
    const int row0 = blockIdx.y * 32, col0 = blockIdx.x * 64;

    // staging: A tile 32x16 = 128 x 16B chunks (1/thread);
    //          W tile 16x64 = 256 chunks (2/thread: rows wk, wk+8)
    const int ar_ = tid >> 2;            // A row 0..31
    const int akc = (tid & 3) * 4;       // A k 0,4,8,12
    const int wk  = tid >> 4;            // W k 0..7 (and +8)
    const int wn  = (tid & 15) * 4;      // W n

    u64 acc[4][2];
    #pragma unroll
    for (int i = 0; i < 4; i++) { acc[i][0] = 0ull; acc[i][1] = 0ull; }

    const int KT = K >> 4;

    auto issue = [&](int kt) {
        const int buf = kt & 3;
        const int k0 = kt * 16;
        const float* pa;
        if (GATHER) {
            int rg = row0 + ar_, k = k0 + akc;
            int bb = rg >> 8, node = rg & 255;
            if (k < 512)       pa = &A [(size_t)rg * 512 + k];
            else if (k < 1024) pa = &g1[(size_t)(bb * 128 + (node >> 1)) * 512 + (k - 512)];
            else               pa = &g2[(size_t)(bb * 64 + (node >> 2)) * 512 + (k - 1024)];
        } else {
            pa = &A[(size_t)(row0 + ar_) * K + k0 + akc];
        }
        cp_async16(smem_u32(&As[buf][ar_][akc]), pa);
        cp_async16(smem_u32(&Ws[buf][wk][wn]),     &W[(size_t)(k0 + wk) * N + col0 + wn]);
        cp_async16(smem_u32(&Ws[buf][wk + 8][wn]), &W[(size_t)(k0 + wk + 8) * N + col0 + wn]);
        cp_commit();
    };

    issue(0); issue(1); issue(2);
    for (int kt = 0; kt < KT; kt++) {
        const int buf = kt & 3;
        cp_wait<2>();
        __syncthreads();

        #pragma unroll
        for (int k = 0; k < 16; k++) {
            float a0 = As[buf][ty * 4 + 0][k];
            float a1 = As[buf][ty * 4 + 1][k];
            float a2 = As[buf][ty * 4 + 2][k];
            float a3 = As[buf][ty * 4 + 3][k];
            u64 d0 = splat2(a0), d1 = splat2(a1), d2 = splat2(a2), d3 = splat2(a3);
            ulonglong2 bq = *(const ulonglong2*)&Ws[buf][k][tx * 4];
            ffma2(acc[0][0], d0, bq.x); ffma2(acc[0][1], d0, bq.y);
            ffma2(acc[1][0], d1, bq.x); ffma2(acc[1][1], d1, bq.y);
            ffma2(acc[2][0], d2, bq.x); ffma2(acc[2][1], d2, bq.y);
            ffma2(acc[3][0], d3, bq.x); ffma2(acc[3][1], d3, bq.y);
        }

        if (kt + 3 < KT) issue(kt + 3);
    }

    float4 bv = make_float4(0.f, 0.f, 0.f, 0.f);
    if (bias) bv = *(const float4*)&bias[col0 + tx * 4];

    float v[4][4];
    #pragma unroll
    for (int i = 0; i < 4; i++) {
        float2 p01 = up2(acc[i][0]);
        float2 p23 = up2(acc[i][1]);
        v[i][0] = p01.x + bv.x; v[i][1] = p01.y + bv.y;
        v[i][2] = p23.x + bv.z; v[i][3] = p23.y + bv.w;
        if (ACT == 1) {
            #pragma unroll
            for (int j = 0; j < 4; j++) v[i][j] = fmaxf(v[i][j], 0.f);
        }
    }

    if (ACT == 2) {
        // pairwise mean over row pairs: write M/2 rows
        #pragma unroll
        for (int p = 0; p < 2; p++) {
            float4 o = make_float4(0.5f * (v[2 * p][0] + v[2 * p + 1][0]),
                                   0.5f * (v[2 * p][1] + v[2 * p + 1][1]),
                                   0.5f * (v[2 * p][2] + v[2 * p + 1][2]),
                                   0.5f * (v[2 * p][3] + v[2 * p + 1][3]));
            *(float4*)&C[(size_t)((row0 >> 1) + ty * 2 + p) * N + col0 + tx * 4] = o;
        }
    } else {
        #pragma unroll
        for (int i = 0; i < 4; i++) {
            *(float4*)&C[(size_t)(row0 + ty * 4 + i) * N + col0 + tx * 4] =
                make_float4(v[i][0], v[i][1], v[i][2], v[i][3]);
        }
    }
}

// ---------------- tf32 helpers (final-MHA-only fast path) --------------------
__device__ __forceinline__ uint32_t tf32_of(float v) {
    uint32_t r; asm("cvt.rna.tf32.f32 %0, %1;" : "=r"(r) : "f"(v)); return r;
}
__device__ __forceinline__ void split2(float v, uint32_t& h, uint32_t& l) {
    h = tf32_of(v);
    l = tf32_of(v - __uint_as_float(h));
}
__device__ __forceinline__ void mma_tf32(float* d, const uint32_t* a, const uint32_t* b) {
    asm("mma.sync.aligned.m16n8k8.row.col.f32.tf32.tf32.f32 "
        "{%0,%1,%2,%3}, {%4,%5,%6,%7}, {%8,%9}, {%0,%1,%2,%3};"
        : "+f"(d[0]), "+f"(d[1]), "+f"(d[2]), "+f"(d[3])
        : "r"(a[0]), "r"(a[1]), "r"(a[2]), "r"(a[3]), "r"(b[0]), "r"(b[1]));
}

// ---------------- tensor-core GEMM (3xTF32, ~1e-5 class) ---------------------
// ONLY for the final sparse-path MHA (feeds output0, threshold 1e-3).
// NOT top-k safe — never use upstream of edge scores.
__global__ __launch_bounds__(256)
void gemm_tc3(const float* __restrict__ A, const float* __restrict__ W,
              const float* __restrict__ bias, float* __restrict__ C,
              int M, int N, int K)
{
    __shared__ uint32_t Ah[2][16][72], Al[2][16][72];
    __shared__ uint32_t Bh[2][16][72], Bl[2][16][72];

    const int tid = threadIdx.x;
    const int lane = tid & 31, wrp = tid >> 5;
    const int row0 = blockIdx.y * 64, col0 = blockIdx.x * 64;
    const int m_w = (wrp >> 2) * 32;
    const int n_w = (wrp & 3) * 16;
    const int g = lane >> 2, tg = lane & 3;

    const int arow = tid >> 2;
    const int akc  = (tid & 3) * 4;
    const int bk   = tid >> 4;
    const int bnc  = (tid & 15) * 4;

    float acc[2][2][4];
    #pragma unroll
    for (int mi = 0; mi < 2; mi++)
        #pragma unroll
        for (int ni = 0; ni < 2; ni++)
            #pragma unroll
            for (int q = 0; q < 4; q++) acc[mi][ni][q] = 0.f;

    const int KT = K >> 4;
    float4 va, vb;

    auto gload = [&](int kt) {
        const int k0 = kt * 16;
        va = *(const float4*)&A[(size_t)(row0 + arow) * K + k0 + akc];
        vb = *(const float4*)&W[(size_t)(k0 + bk) * N + col0 + bnc];
    };
    auto sstore = [&](int buf) {
        uint32_t h, l;
        split2(va.x, h, l); Ah[buf][akc + 0][arow] = h; Al[buf][akc + 0][arow] = l;
        split2(va.y, h, l); Ah[buf][akc + 1][arow] = h; Al[buf][akc + 1][arow] = l;
        split2(va.z, h, l); Ah[buf][akc + 2][arow] = h; Al[buf][akc + 2][arow] = l;
        split2(va.w, h, l); Ah[buf][akc + 3][arow] = h; Al[buf][akc + 3][arow] = l;
        uint4 h4, l4;
        split2(vb.x, h4.x, l4.x);
        split2(vb.y, h4.y, l4.y);
        split2(vb.z, h4.z, l4.z);
        split2(vb.w, h4.w, l4.w);
        *(uint4*)&Bh[buf][bk][bnc] = h4;
        *(uint4*)&Bl[buf][bk][bnc] = l4;
    };

    gload(0); sstore(0);
    __syncthreads();
    for (int kt = 0; kt < KT; kt++) {
        const int buf = kt & 1;
        if (kt + 1 < KT) gload(kt + 1);
        #pragma unroll
        for (int ks = 0; ks < 16; ks += 8) {
            uint32_t ah[2][4], al[2][4], bh[2][2], bl[2][2];
            #pragma unroll
            for (int mi = 0; mi < 2; mi++) {
                const int m = m_w + mi * 16;
                ah[mi][0] = Ah[buf][ks + tg][m + g];
                ah[mi][1] = Ah[buf][ks + tg][m + g + 8];
                ah[mi][2] = Ah[buf][ks + tg + 4][m + g];
                ah[mi][3] = Ah[buf][ks + tg + 4][m + g + 8];
                al[mi][0] = Al[buf][ks + tg][m + g];
                al[mi][1] = Al[buf][ks + tg][m + g + 8];
                al[mi][2] = Al[buf][ks + tg + 4][m + g];
                al[mi][3] = Al[buf][ks + tg + 4][m + g + 8];
            }
            #pragma unroll
            for (int ni = 0; ni < 2; ni++) {
                const int n = n_w + ni * 8;
                bh[ni][0] = Bh[buf][ks + tg][n + g];
                bh[ni][1] = Bh[buf][ks + tg + 4][n + g];
                bl[ni][0] = Bl[buf][ks + tg][n + g];
                bl[ni][1] = Bl[buf][ks + tg + 4][n + g];
            }
            #pragma unroll
            for (int mi = 0; mi < 2; mi++)
                #pragma unroll
                for (int ni = 0; ni < 2; ni++) {
                    mma_tf32(acc[mi][ni], al[mi], bh[ni]);
                    mma_tf32(acc[mi][ni], ah[mi], bl[ni]);
                    mma_tf32(acc[mi][ni], ah[mi], bh[ni]);
                }
        }
        if (kt + 1 < KT) sstore(buf ^ 1);
        __syncthreads();
    }

    #pragma unroll
    for (int mi = 0; mi < 2; mi++) {
        #pragma unroll
        for (int ni = 0; ni < 2; ni++) {
            const int col = col0 + n_w + ni * 8 + 2 * tg;
            float b0 = 0.f, b1 = 0.f;
            if (bias) { b0 = bias[col]; b1 = bias[col + 1]; }
            const int r0 = row0 + m_w + mi * 16 + g;
            *(float2*)&C[(size_t)r0 * N + col] =
                make_float2(acc[mi][ni][0] + b0, acc[mi][ni][1] + b1);
            *(float2*)&C[(size_t)(r0 + 8) * N + col] =
                make_float2(acc[mi][ni][2] + b0, acc[mi][ni][3] + b1);
        }
    }
}

// ---------------- fused flash attention --------------------------------------
// grid (n/32, B*H), 128 threads. qkv [B,n,1536]; out att [B*n, 512] head-packed.
__global__ __launch_bounds__(128)
void flash_attn(const float* __restrict__ qkv, float* __restrict__ att, int n)
{
    __shared__ __align__(16) float Qs[64][36];   // [k][i] transposed
    __shared__ __align__(16) float Ks[64][36];   // [k][j] transposed, 32-j chunk
    __shared__ __align__(16) float Vs[32][68];   // [j][d]
    __shared__ __align__(16) float Ps[32][36];   // [i][j]
    const int bh = blockIdx.y, b = bh >> 3, h = bh & 7;
    const int i0 = blockIdx.x * 32;
    const int tid = threadIdx.x;
    const int tx = tid & 7, ty = tid >> 3;       // ty 0..15 (2 rows), tx 0..7
    const float* qb = qkv + (size_t)b * n * 1536 + h * 64;
    const float* kb = qb + 512;
    const float* vb = qb + 1024;

    #pragma unroll
    for (int t = 0; t < 4; t++) {
        int f = t * 128 + tid;                   // 0..511
        int r = f >> 4, c = (f & 15) * 4;
        float4 q = *(const float4*)&qb[(size_t)(i0 + r) * 1536 + c];
        Qs[c + 0][r] = q.x; Qs[c + 1][r] = q.y; Qs[c + 2][r] = q.z; Qs[c + 3][r] = q.w;
    }

    float Oa[2][8] = {};
    float m[2] = {-1e30f, -1e30f}, l[2] = {0.f, 0.f};

    for (int j0 = 0; j0 < n; j0 += 32) {
        __syncthreads();
        #pragma unroll
        for (int t = 0; t < 4; t++) {
            int f = t * 128 + tid;
            int r = f >> 4, c = (f & 15) * 4;
            float4 kv = *(const float4*)&kb[(size_t)(j0 + r) * 1536 + c];
            Ks[c + 0][r] = kv.x; Ks[c + 1][r] = kv.y; Ks[c + 2][r] = kv.z; Ks[c + 3][r] = kv.w;
            *(float4*)&Vs[r][c] = *(const float4*)&vb[(size_t)(j0 + r) * 1536 + c];
        }
        __syncthreads();

        float s[2][4] = {};
        #pragma unroll
        for (int k = 0; k < 64; k++) {
            float2 q2 = *(const float2*)&Qs[k][ty * 2];
            float4 k4 = *(const float4*)&Ks[k][tx * 4];
            s[0][0] += q2.x * k4.x; s[0][1] += q2.x * k4.y;
            s[0][2] += q2.x * k4.z; s[0][3] += q2.x * k4.w;
            s[1][0] += q2.y * k4.x; s[1][1] += q2.y * k4.y;
            s[1][2] += q2.y * k4.z; s[1][3] += q2.y * k4.w;
        }

        float p[2][4];
        #pragma unroll
        for (int i = 0; i < 2; i++) {
            #pragma unroll
            for (int j = 0; j < 4; j++) s[i][j] *= 0.125f;
            float mc = fmaxf(fmaxf(s[i][0], s[i][1]), fmaxf(s[i][2], s[i][3]));
            #pragma unroll
            for (int o = 1; o < 8; o <<= 1) mc = fmaxf(mc, __shfl_xor_sync(0xffffffffu, mc, o));
            float mn = fmaxf(m[i], mc);
            float sc = expf(m[i] - mn);
            m[i] = mn;
            float ls = 0.f;
            #pragma unroll
            for (int j = 0; j < 4; j++) { p[i][j] = expf(s[i][j] - mn); ls += p[i][j]; }
            #pragma unroll
            for (int o = 1; o < 8; o <<= 1) ls += __shfl_xor_sync(0xffffffffu, ls, o);
            l[i] = l[i] * sc + ls;
            #pragma unroll
            for (int d = 0; d < 8; d++) Oa[i][d] *= sc;
            *(float4*)&Ps[2 * ty + i][tx * 4] = make_float4(p[i][0], p[i][1], p[i][2], p[i][3]);
        }
        __syncthreads();

        #pragma unroll
        for (int j = 0; j < 32; j++) {
            float p0 = Ps[2 * ty][j], p1 = Ps[2 * ty + 1][j];
            float4 v0 = *(const float4*)&Vs[j][tx * 8];
            float4 v1 = *(const float4*)&Vs[j][tx * 8 + 4];
            Oa[0][0] += p0 * v0.x; Oa[0][1] += p0 * v0.y; Oa[0][2] += p0 * v0.z; Oa[0][3] += p0 * v0.w;
            Oa[0][4] += p0 * v1.x; Oa[0][5] += p0 * v1.y; Oa[0][6] += p0 * v1.z; Oa[0][7] += p0 * v1.w;
            Oa[1][0] += p1 * v0.x; Oa[1][1] += p1 * v0.y; Oa[1][2] += p1 * v0.z; Oa[1][3] += p1 * v0.w;
            Oa[1][4] += p1 * v1.x; Oa[1][5] += p1 * v1.y; Oa[1][6] += p1 * v1.z; Oa[1][7] += p1 * v1.w;
        }
    }

    #pragma unroll
    for (int i = 0; i < 2; i++) {
        const float inv = 1.f / l[i];
        float* op = att + (size_t)(b * n + i0 + 2 * ty + i) * 512 + h * 64 + tx * 8;
        *(float4*)op       = make_float4(Oa[i][0] * inv, Oa[i][1] * inv, Oa[i][2] * inv, Oa[i][3] * inv);
        *(float4*)(op + 4) = make_float4(Oa[i][4] * inv, Oa[i][5] * inv, Oa[i][6] * inv, Oa[i][7] * inv);
    }
}

// ---------------- LayerNorm over rows of 512 --------------------------------
__global__ __launch_bounds__(256)
void ln_rows(const float* __restrict__ Hp, const float* __restrict__ g,
             const float* __restrict__ bb, float* __restrict__ out, int rows)
{
    const int warp = (blockIdx.x * 256 + threadIdx.x) >> 5;
    const int lane = threadIdx.x & 31;
    if (warp >= rows) return;
    const float* row = Hp + (size_t)warp * 512;
    float v[16];
    float s = 0.f;
    #pragma unroll
    for (int t = 0; t < 16; t++) { v[t] = row[lane + 32 * t]; s += v[t]; }
    #pragma unroll
    for (int o = 16; o; o >>= 1) s += __shfl_xor_sync(0xffffffffu, s, o);
    const float mean = s * (1.f / 512.f);
    float var = 0.f;
    #pragma unroll
    for (int t = 0; t < 16; t++) { float d = v[t] - mean; var += d * d; }
    #pragma unroll
    for (int o = 16; o; o >>= 1) var += __shfl_xor_sync(0xffffffffu, var, o);
    var *= (1.f / 512.f);
    const float inv = rsqrtf(var + 1e-5f);
    float* o_ = out + (size_t)warp * 512;
    #pragma unroll
    for (int t = 0; t < 16; t++) {
        int c = lane + 32 * t;
        o_[c] = (v[t] - mean) * inv * g[c] + bb[c];
    }
}

// ---------------- fused edge scores + top-25 ---------------------------------
// Block = (b, 8 rows i). Phase 1: warp w computes scores for j in [32w,32w+32)
// for all 8 rows (IDENTICAL fp ops + warp-reduce order as before) into smem.
// Phase 2: warp w selects top-25 of row i0+w (same lexicographic tie-break)
// and writes the one-hot adj row directly.
__global__ __launch_bounds__(256)
void edge_topk(const float* __restrict__ hi, const float* __restrict__ hj,
               const float* __restrict__ We2, const float* __restrict__ be2,
               float* __restrict__ adj)
{
    __shared__ float his[8][512];
    __shared__ float w2s[512];
    __shared__ float sc8[8][260];
    const int blk = blockIdx.x;
    const int b = blk >> 5;
    const int i0 = (blk & 31) * 8;
    const int tid = threadIdx.x;
    #pragma unroll
    for (int q = 0; q < 4; q++) {
        int fi = tid + 256 * q;
        int r = fi >> 7;
        int c = (fi & 127) * 4;
        *(float4*)&his[r][c] = *(const float4*)&hi[(size_t)(b * 256 + i0 + r) * 512 + c];
    }
    w2s[tid] = We2[tid];
    w2s[tid + 256] = We2[tid + 256];
    __syncthreads();

    const int w = tid >> 5, lane = tid & 31;
    const float be2v = be2[0];
    const float* hjb = hj + (size_t)b * 256 * 512;
    for (int jj = 0; jj < 32; jj++) {
        const int j = w * 32 + jj;
        const float* hjr = hjb + (size_t)j * 512;
        float acc[8] = {};
        #pragma unroll 4
        for (int q = 0; q < 16; q++) {
            int d = lane + 32 * q;
            float hv = hjr[d];
            float w2 = w2s[d];
            #pragma unroll
            for (int i = 0; i < 8; i++)
                acc[i] += fmaxf(his[i][d] + hv, 0.f) * w2;
        }
        #pragma unroll
        for (int i = 0; i < 8; i++) {
            float a = acc[i];
            #pragma unroll
            for (int o = 16; o; o >>= 1) a += __shfl_xor_sync(0xffffffffu, a, o);
            acc[i] = a;
        }
        if (lane == 0) {
            #pragma unroll
            for (int i = 0; i < 8; i++) {
                int ii = i0 + i;
                float sv = (j == ii) ? 0.f : 1.f / (1.f + expf(-(acc[i] + be2v)));
                sc8[i][j] = sv;
            }
        }
    }
    __syncthreads();

    // Phase 2: warp w -> row i0 + w
    const int row = b * 256 + i0 + w;
    float* arow = adj + (size_t)row * N_;
    float v[8];
    #pragma unroll
    for (int t = 0; t < 8; t++) { v[t] = sc8[w][lane + 32 * t]; arow[lane + 32 * t] = 0.f; }
    __syncwarp();
    for (int k = 0; k < KSP_; k++) {
        float bvv = -1e30f; int bi = 0x7fffffff;
        #pragma unroll
        for (int t = 0; t < 8; t++) {
            int idx = lane + 32 * t;
            if (v[t] > bvv) { bvv = v[t]; bi = idx; }
        }
        #pragma unroll
        for (int o = 16; o; o >>= 1) {
            float ov = __shfl_xor_sync(0xffffffffu, bvv, o);
            int   oi = __shfl_xor_sync(0xffffffffu, bi, o);
            if (ov > bvv || (ov == bvv && oi < bi)) { bvv = ov; bi = oi; }
        }
        if (lane == (bi & 31)) v[bi >> 5] = -1e30f;
        if (lane == 0) arow[bi] = 1.0f;
    }
}

// ---------------- host orchestration ----------------------------------------
#define GS(ACT, GATHER, GX, GY, GZ, ...) \
    gemmS<ACT, GATHER><<<dim3(GX, GY, GZ), 128>>>(__VA_ARGS__)

// scalar (proven) MHA — used for all hierarchy levels (score-feeding path)
static void run_mha_scalar(const float* cur, const float* Wqkv, const float* bqkv,
                           const float* Wo, const float* bo, float* outp,
                           float* qkv, float* att, int n)
{
    const int M = B_ * n;
    GS(0, 0, 1536 / 64, M / 32, 1,
       cur, Wqkv, bqkv, qkv, M, 1536, 512, nullptr, nullptr, nullptr, nullptr, nullptr);
    flash_attn<<<dim3(n / 32, B_ * H_), 128>>>(qkv, att, n);
    GS(0, 0, 512 / 64, M / 32, 1,
       att, Wo, bo, outp, M, 512, 512, nullptr, nullptr, nullptr, nullptr, nullptr);
}

// tensor-core MHA — used ONLY for the final sparse-path MHA (output0 slack)
static void run_mha_tc(const float* cur, const float* Wqkv, const float* bqkv,
                       const float* Wo, const float* bo, float* outp,
                       float* qkv, float* att, int n)
{
    const int M = B_ * n;
    gemm_tc3<<<dim3(1536 / 64, M / 64), 256>>>(cur, Wqkv, bqkv, qkv, M, 1536, 512);
    flash_attn<<<dim3(n / 32, B_ * H_), 128>>>(qkv, att, n);
    gemm_tc3<<<dim3(512 / 64, M / 64), 256>>>(att, Wo, bo, outp, M, 512, 512);
}

extern "C" void kernel_launch(void* const* d_in, const int* in_sizes, int n_in,
                              void* d_out, int out_size)
{
    const float* x      = (const float*)d_in[0];
    const float* Wqkv   = (const float*)d_in[2];
    const float* bqkv   = (const float*)d_in[3];
    const float* Wo     = (const float*)d_in[4];
    const float* bo     = (const float*)d_in[5];
    const float* Wp1    = (const float*)d_in[6];
    const float* bp1    = (const float*)d_in[7];
    const float* Wp2    = (const float*)d_in[8];
    const float* bp2    = (const float*)d_in[9];
    const float* Wfuse  = (const float*)d_in[10];
    const float* bfuse  = (const float*)d_in[11];
    const float* ln_g   = (const float*)d_in[12];
    const float* ln_b   = (const float*)d_in[13];
    const float* We1    = (const float*)d_in[14];
    const float* be1    = (const float*)d_in[15];
    const float* We2    = (const float*)d_in[16];
    const float* be2    = (const float*)d_in[17];
    const float* Ws_qkv = (const float*)d_in[18];
    const float* bs_qkv = (const float*)d_in[19];
    const float* Ws_o   = (const float*)d_in[20];
    const float* bs_o   = (const float*)d_in[21];
    float* out = (float*)d_out;

    float* sc = nullptr;
    cudaGetSymbolAddress((void**)&sc, g_scratch);
    float* qkv  = sc + OFF_QKV;
    float* att  = sc + OFF_ATT;
    float* a0   = sc + OFF_A0;
    float* a1   = sc + OFF_A1;
    float* a2   = sc + OFF_A2;
    float* cur1 = sc + OFF_CUR1;
    float* cur2 = sc + OFF_CUR2;
    float* p1   = sc + OFF_P1;
    float* p2   = sc + OFF_P2;
    float* hier = sc + OFF_HIER;
    float* hi   = sc + OFF_HI;
    float* hj   = sc + OFF_HJ;

    // ---- hierarchy (score-feeding: scalar proven numerics) ----
    const int ns[3] = {256, 128, 64};
    float* aouts[3] = {a0, a1, a2};
    float* curbuf[2] = {cur1, cur2};
    const float* cur = x;
    for (int l = 0; l < 3; l++) {
        const int n = ns[l];
        const int M = B_ * n;
        run_mha_scalar(cur, Wqkv + (size_t)l * 512 * 1536, bqkv + l * 1536,
                       Wo + (size_t)l * 512 * 512, bo + l * 512, aouts[l], qkv, att, n);
        if (l < 2) {
            GS(1, 0, 256 / 64, M / 32, 1,
               aouts[l], Wp1 + (size_t)l * 512 * 256, bp1 + l * 256, p1, M, 256, 512,
               nullptr, nullptr, nullptr, nullptr, nullptr);
            // Wp2 with fused pairwise-mean epilogue -> writes M/2 rows directly
            GS(2, 0, 512 / 64, M / 32, 1,
               p1, Wp2 + (size_t)l * 256 * 512, bp2 + l * 512, curbuf[l], M, 512, 256,
               nullptr, nullptr, nullptr, nullptr, nullptr);
            cur = curbuf[l];
        }
    }

    // ---- fuse (gathered concat) + LN (score-feeding: scalar) ----
    GS(1, 1, 512 / 64, 1024 / 32, 1,
       a0, Wfuse, bfuse, p2, 1024, 512, 1536, a1, a2, nullptr, nullptr, nullptr);
    ln_rows<<<1024 / 8, 256>>>(p2, ln_g, ln_b, hier, 1024);

    // ---- edge scoring (hi+hj fused via z; scalar) + fused top-k ----
    GS(0, 0, 512 / 64, 1024 / 32, 2,
       hier, We1, nullptr, hi, 1024, 512, 512,
       nullptr, nullptr, We1 + 512 * 512, be1, hj);
    float* adj_out = out + (size_t)B_ * N_ * D_;
    edge_topk<<<B_ * (N_ / 8), 256>>>(hi, hj, We2, be2, adj_out);

    // ---- final sparse-path MHA -> attended (output0 only: tensor cores) ----
    run_mha_tc(hier, Ws_qkv, bs_qkv, Ws_o, bs_o, out, qkv, att, 256);
}